// round 4
// baseline (speedup 1.0000x reference)
#include <cuda_runtime.h>
#include <cstdint>

constexpr int   B = 8, F = 16, K = 24;
constexpr int   L = 384 * 384;          // 147456 pixels per (b, plane)
constexpr float EPSV       = 1e-8f;
constexpr float DELTA_VAR  = 0.5f;
constexpr float DELTA_DIST = 1.5f;
constexpr float GAMMA      = 0.001f;

// Scratch (device globals: no allocation allowed)
__device__ float g_sums[B * F * K];
__device__ float g_tsum[B * K];
__device__ float g_means[B * F * K];
__device__ float g_m2[B * K];
__device__ float g_factor[B * K];
__device__ float g_acc[4];              // [0]=dist_term/B  [1]=reg_sum/B  [2]=var accumulator
__device__ unsigned g_ticket;
__device__ unsigned char g_labels[B * L];

// ---------------------------------------------------------------------------
// K0: zero the accumulators (graph replays must be deterministic)
// ---------------------------------------------------------------------------
__global__ void k_init() {
    int i = blockIdx.x * blockDim.x + threadIdx.x;
    if (i < B * F * K) g_sums[i] = 0.f;
    if (i < B * K) g_tsum[i] = 0.f;
    if (i < 4) g_acc[i] = 0.f;
    if (i == 0) g_ticket = 0u;
}

// ---------------------------------------------------------------------------
// K1: sums[b,f,c] = sum_l x[b,f,l]*t[b,c,l];  t_sum[b,c]; per-pixel labels.
// 128 pixels/tile, 8 tiles/block, grid (144, 8); register double-buffered;
// compute phase uses packed fma.rn.f32x2 (2 pixels per FFMA2).
// ---------------------------------------------------------------------------
constexpr int TP  = 128;
constexpr int TPB = 8;
constexpr int NCHUNK = L / (TP * TPB);   // 144
constexpr int XST = 132;                 // padded row stride (floats); 132*4=528 is 16B-aligned

__global__ __launch_bounds__(256) void k_sums(const float* __restrict__ x,
                                              const float* __restrict__ t) {
    __shared__ __align__(16) float pool[6144];   // tiles / reduction buffer union
    __shared__ unsigned char labels_s[TP];
    float* Xs = pool;                    // [16][132]
    float* Ts = pool + F * XST;          // [24][132]

    const int tid  = threadIdx.x;
    const int w    = tid >> 5;           // warp 0..7
    const int lane = tid & 31;
    const int b    = blockIdx.y;
    const int g    = tid >> 4;           // group 0..15
    const int fi   = tid & 15;           // feature row for compute phase
    const float* xb = x + (size_t)(b * F) * L;
    const float* tb = t + (size_t)(b * K) * L;

    unsigned long long acc2[K];
#pragma unroll
    for (int c = 0; c < K; c++) acc2[c] = 0ull;
    float ts0 = 0.f, ts1 = 0.f, ts2 = 0.f;

    const int l0b = blockIdx.x * (TP * TPB);

    // x-load geometry: warp w owns feature rows 2w,2w+1; lanes 0-15 row 2w,
    // lanes 16-31 row 2w+1; each lane one 256-bit evict_last load (8 floats).
    const int xf_row = 2 * w + (lane >> 4);
    const int xoff   = (lane & 15) * 8;

    // staging registers (tile i+1 loaded while computing tile i)
    uint32_t xr[8];
    float4 tr0, tr1, tr2;

#define LOAD_TILE(L0)                                                         \
    {                                                                         \
        const float* p = xb + (size_t)xf_row * L + (L0) + xoff;               \
        asm volatile(                                                         \
            "ld.global.L2::evict_last.v8.b32 {%0,%1,%2,%3,%4,%5,%6,%7}, [%8];"\
            : "=r"(xr[0]), "=r"(xr[1]), "=r"(xr[2]), "=r"(xr[3]),             \
              "=r"(xr[4]), "=r"(xr[5]), "=r"(xr[6]), "=r"(xr[7])              \
            : "l"(p));                                                        \
        tr0 = __ldcs((const float4*)(tb + (size_t)(3 * w + 0) * L + (L0) + lane * 4)); \
        tr1 = __ldcs((const float4*)(tb + (size_t)(3 * w + 1) * L + (L0) + lane * 4)); \
        tr2 = __ldcs((const float4*)(tb + (size_t)(3 * w + 2) * L + (L0) + lane * 4)); \
    }

    LOAD_TILE(l0b);

    for (int tile = 0; tile < TPB; ++tile) {
        const int l0 = l0b + tile * TP;

        __syncthreads();                  // previous compute done; smem free

        // ---- store staged regs to smem; labels + t_sum from regs ----
        {
            uint4* s = (uint4*)(Xs + xf_row * XST + xoff);
            s[0] = make_uint4(xr[0], xr[1], xr[2], xr[3]);
            s[1] = make_uint4(xr[4], xr[5], xr[6], xr[7]);

            const int p0 = lane * 4;
            float4 v = tr0;  int c = 3 * w;
            ts0 += (v.x + v.y) + (v.z + v.w);
            *(float4*)(Ts + c * XST + p0) = v;
            if (v.x != 0.f) labels_s[p0 + 0] = (unsigned char)c;
            if (v.y != 0.f) labels_s[p0 + 1] = (unsigned char)c;
            if (v.z != 0.f) labels_s[p0 + 2] = (unsigned char)c;
            if (v.w != 0.f) labels_s[p0 + 3] = (unsigned char)c;
            v = tr1;  c = 3 * w + 1;
            ts1 += (v.x + v.y) + (v.z + v.w);
            *(float4*)(Ts + c * XST + p0) = v;
            if (v.x != 0.f) labels_s[p0 + 0] = (unsigned char)c;
            if (v.y != 0.f) labels_s[p0 + 1] = (unsigned char)c;
            if (v.z != 0.f) labels_s[p0 + 2] = (unsigned char)c;
            if (v.w != 0.f) labels_s[p0 + 3] = (unsigned char)c;
            v = tr2;  c = 3 * w + 2;
            ts2 += (v.x + v.y) + (v.z + v.w);
            *(float4*)(Ts + c * XST + p0) = v;
            if (v.x != 0.f) labels_s[p0 + 0] = (unsigned char)c;
            if (v.y != 0.f) labels_s[p0 + 1] = (unsigned char)c;
            if (v.z != 0.f) labels_s[p0 + 2] = (unsigned char)c;
            if (v.w != 0.f) labels_s[p0 + 3] = (unsigned char)c;
        }
        __syncthreads();

        // labels -> gmem (coalesced)
        if (tid < TP / 4) {
            uint32_t lv = *(const uint32_t*)&labels_s[tid * 4];
            *(uint32_t*)(g_labels + (size_t)b * L + l0 + tid * 4) = lv;
        }

        // prefetch next tile into regs (overlaps with compute below)
        if (tile + 1 < TPB) LOAD_TILE(l0 + TP);

        // ---- compute: packed f32x2 FFMA; group g covers quads 2g,2g+1 ----
        const float* Xrow = Xs + fi * XST;
#pragma unroll
        for (int qi = 0; qi < 2; ++qi) {
            const int q = (g * 2 + qi) * 4;
            const ulonglong2 xf = *(const ulonglong2*)(Xrow + q);
#pragma unroll
            for (int c = 0; c < K; c++) {
                const ulonglong2 tv = *(const ulonglong2*)(Ts + c * XST + q);
                asm("fma.rn.f32x2 %0, %1, %2, %0;"
                    : "+l"(acc2[c]) : "l"(xf.x), "l"(tv.x));
                asm("fma.rn.f32x2 %0, %1, %2, %0;"
                    : "+l"(acc2[c]) : "l"(xf.y), "l"(tv.y));
            }
        }
    }
#undef LOAD_TILE

    // ---- block reduction of acc across the 16 groups ----
    __syncthreads();                      // done reading Ts; reuse pool
#pragma unroll
    for (int c = 0; c < K; c++) {
        const float lo = __uint_as_float((uint32_t)(acc2[c] & 0xffffffffull));
        const float hi = __uint_as_float((uint32_t)(acc2[c] >> 32));
        pool[tid * K + c] = lo + hi;
    }
    __syncthreads();
    for (int i = tid; i < F * K; i += 256) {      // F*K=384 > 256 threads
        const int f = i / K, c = i % K;
        float s = 0.f;
#pragma unroll
        for (int gg = 0; gg < 16; gg++) s += pool[(gg * 16 + f) * K + c];
        atomicAdd(&g_sums[(b * F + f) * K + c], s);
    }
#pragma unroll
    for (int off = 16; off; off >>= 1) {
        ts0 += __shfl_down_sync(0xffffffffu, ts0, off);
        ts1 += __shfl_down_sync(0xffffffffu, ts1, off);
        ts2 += __shfl_down_sync(0xffffffffu, ts2, off);
    }
    if (lane == 0) {
        atomicAdd(&g_tsum[b * K + 3 * w + 0], ts0);
        atomicAdd(&g_tsum[b * K + 3 * w + 1], ts1);
        atomicAdd(&g_tsum[b * K + 3 * w + 2], ts2);
    }
}

// ---------------------------------------------------------------------------
// K2: means, m2, per-cluster variance factor, pairwise-distance + reg terms.
// One block per b, 576 threads (= 24*24 pairs).
// ---------------------------------------------------------------------------
__global__ void k_means(const int* __restrict__ n_clusters) {
    __shared__ float ms[F * K];
    __shared__ float m2s[K];
    __shared__ float red[32];

    const int b   = blockIdx.x;
    const int tid = threadIdx.x;
    const int nc  = n_clusters[b];
    const float ncf = (float)nc;

    if (tid < F * K) {
        const int c = tid % K;
        float m = g_sums[b * F * K + tid] / (g_tsum[b * K + c] + EPSV);
        m = (c < nc) ? m : 0.f;
        ms[tid] = m;
        g_means[b * F * K + tid] = m;
    }
    __syncthreads();
    if (tid < K) {
        float m2 = 0.f;
#pragma unroll
        for (int f = 0; f < F; f++) { const float v = ms[f * K + tid]; m2 += v * v; }
        m2s[tid] = m2;
        g_m2[b * K + tid] = m2;
        // factor[c] = valid / (t_sum+eps) / (nc+eps) / B   (nc>0 implied by c<nc)
        const float ts = g_tsum[b * K + tid];
        g_factor[b * K + tid] = (tid < nc)
            ? (1.f / (ts + EPSV)) * (1.f / (ncf + EPSV)) * (1.f / (float)B) : 0.f;
    }
    __syncthreads();

    float regp = 0.f;
    if (tid < K && tid < nc) {
        const float m2 = m2s[tid];
        regp = (m2 > 0.f) ? sqrtf(m2) : 0.f;
    }
    float hs = 0.f;
    {
        const int cc = tid / K, dd = tid % K;
        if (cc != dd && cc < nc && dd < nc) {
            float mm = 0.f;
#pragma unroll
            for (int f = 0; f < F; f++) mm += ms[f * K + cc] * ms[f * K + dd];
            float pd2 = fmaxf(m2s[cc] - 2.f * mm + m2s[dd], 0.f);
            const float pdist = (pd2 > 0.f) ? sqrtf(pd2) : 0.f;
            const float h = fmaxf(2.f * DELTA_DIST - pdist, 0.f);
            hs = h * h;
        }
    }
    const int lane = tid & 31, wid = tid >> 5;   // 18 warps
#pragma unroll
    for (int off = 16; off; off >>= 1) hs += __shfl_down_sync(0xffffffffu, hs, off);
    if (lane == 0) red[wid] = hs;
    __syncthreads();
    float hs_tot = 0.f;
    if (tid < 32) {
        float v = (tid < 18) ? red[tid] : 0.f;
#pragma unroll
        for (int off = 16; off; off >>= 1) v += __shfl_down_sync(0xffffffffu, v, off);
        hs_tot = v;
    }
    __syncthreads();
#pragma unroll
    for (int off = 16; off; off >>= 1) regp += __shfl_down_sync(0xffffffffu, regp, off);
    if (lane == 0) red[wid] = regp;
    __syncthreads();
    if (tid == 0) {
        float reg_tot = 0.f;
        for (int i = 0; i < 18; i++) reg_tot += red[i];
        const float dist_per = hs_tot / (2.f * ncf * (ncf - 1.f) + EPSV);
        if (nc > 1) atomicAdd(&g_acc[0], dist_per / (float)B);
        if (nc > 0) atomicAdd(&g_acc[1], reg_tot / ncf / (float)B);
    }
}

// ---------------------------------------------------------------------------
// K3: variance term, fully folded: each pixel adds h^2 * factor[label] to one
// scalar; block reduce -> 1 global atomic; last block writes the output.
// grid (144, 8), 256 threads, 4 pixels/thread.
// ---------------------------------------------------------------------------
__global__ __launch_bounds__(256) void k_var(const float* __restrict__ x,
                                             float* __restrict__ out) {
    __shared__ float ms[F * K];
    __shared__ float m2s[K];
    __shared__ float fac[K];
    __shared__ float red[8];

    const int b   = blockIdx.y;
    const int tid = threadIdx.x;
    for (int i = tid; i < F * K; i += 256) ms[i] = g_means[b * F * K + i];
    if (tid < K) { m2s[tid] = g_m2[b * K + tid]; fac[tid] = g_factor[b * K + tid]; }
    __syncthreads();

    const int l = blockIdx.x * 1024 + tid * 4;
    const uint32_t lab4 = __ldg((const uint32_t*)(g_labels + (size_t)b * L + l));
    const int lab0 = (int)(lab4 & 255),        lab1 = (int)((lab4 >> 8) & 255);
    const int lab2 = (int)((lab4 >> 16) & 255), lab3 = (int)((lab4 >> 24) & 255);

    float x20 = 0.f, x21 = 0.f, x22 = 0.f, x23 = 0.f;
    float xm0 = 0.f, xm1 = 0.f, xm2 = 0.f, xm3 = 0.f;
    const float* xb = x + (size_t)(b * F) * L + l;
    const float* ms0 = ms + lab0; const float* ms1 = ms + lab1;
    const float* ms2 = ms + lab2; const float* ms3 = ms + lab3;
#pragma unroll
    for (int f = 0; f < F; f++) {
        const float4 v = __ldg((const float4*)(xb + (size_t)f * L));
        x20 += v.x * v.x;  xm0 += v.x * ms0[f * K];
        x21 += v.y * v.y;  xm1 += v.y * ms1[f * K];
        x22 += v.z * v.z;  xm2 += v.z * ms2[f * K];
        x23 += v.w * v.w;  xm3 += v.w * ms3[f * K];
    }
    float a = 0.f;
    {
        float d2 = fmaxf(x20 - 2.f * xm0 + m2s[lab0], 0.f);
        float h = ((d2 > 0.f) ? sqrtf(d2) : 0.f) - DELTA_VAR;
        if (h > 0.f) a += h * h * fac[lab0];
        d2 = fmaxf(x21 - 2.f * xm1 + m2s[lab1], 0.f);
        h = ((d2 > 0.f) ? sqrtf(d2) : 0.f) - DELTA_VAR;
        if (h > 0.f) a += h * h * fac[lab1];
        d2 = fmaxf(x22 - 2.f * xm2 + m2s[lab2], 0.f);
        h = ((d2 > 0.f) ? sqrtf(d2) : 0.f) - DELTA_VAR;
        if (h > 0.f) a += h * h * fac[lab2];
        d2 = fmaxf(x23 - 2.f * xm3 + m2s[lab3], 0.f);
        h = ((d2 > 0.f) ? sqrtf(d2) : 0.f) - DELTA_VAR;
        if (h > 0.f) a += h * h * fac[lab3];
    }
    // block reduce
    const int lane = tid & 31, wid = tid >> 5;
#pragma unroll
    for (int off = 16; off; off >>= 1) a += __shfl_down_sync(0xffffffffu, a, off);
    if (lane == 0) red[wid] = a;
    __syncthreads();
    if (tid == 0) {
        float s = 0.f;
#pragma unroll
        for (int i = 0; i < 8; i++) s += red[i];
        atomicAdd(&g_acc[2], s);
        __threadfence();
        const unsigned t = atomicAdd(&g_ticket, 1u);
        if (t == (unsigned)(NCHUNK * B) - 1u) {
            volatile float* ga = g_acc;
            out[0] = ga[2] + ga[0] + GAMMA * ga[1];
        }
    }
}

// ---------------------------------------------------------------------------
extern "C" void kernel_launch(void* const* d_in, const int* in_sizes, int n_in,
                              void* d_out, int out_size) {
    const float* x  = (const float*)d_in[0];
    const float* t  = (const float*)d_in[1];
    const int*   nc = (const int*)d_in[2];
    float* out = (float*)d_out;

    k_init<<<12, 256>>>();
    k_sums<<<dim3(NCHUNK, B), 256>>>(x, t);
    k_means<<<B, 576>>>(nc);
    k_var<<<dim3(NCHUNK, B), 256>>>(x, out);
}

// round 5
// speedup vs baseline: 1.2790x; 1.2790x over previous
#include <cuda_runtime.h>
#include <cstdint>

constexpr int   B = 8, F = 16, K = 24;
constexpr int   L = 384 * 384;          // 147456 pixels per (b, plane)
constexpr float EPSV       = 1e-8f;
constexpr float DELTA_VAR  = 0.5f;
constexpr float DELTA_DIST = 1.5f;
constexpr float GAMMA      = 0.001f;

// Scratch (device globals: no allocation allowed)
__device__ float g_sums[B * F * K];
__device__ float g_tsum[B * K];
__device__ float g_means[B * F * K];
__device__ float g_m2[B * K];
__device__ float g_factor[B * K];
__device__ float g_acc[4];              // [0]=dist/B [1]=reg/B [2]=var accumulator
__device__ unsigned g_ticket;
__device__ unsigned char g_labels[B * L];

// ---------------------------------------------------------------------------
// K0: zero accumulators (graph replays must be deterministic)
// ---------------------------------------------------------------------------
__global__ void k_init() {
    int i = blockIdx.x * blockDim.x + threadIdx.x;
    if (i < B * F * K) g_sums[i] = 0.f;
    if (i < B * K) g_tsum[i] = 0.f;
    if (i < 4) g_acc[i] = 0.f;
    if (i == 0) g_ticket = 0u;
}

// ---------------------------------------------------------------------------
// K1: sums[b,f,c] = sum_l x[b,f,l]*t[b,c,l];  t_sum; labels.
// Exploits validity: t rows c >= n_clusters[b] are all-zero -> neither loaded
// nor multiplied. Compute uses packed fma.rn.f32x2 with early break at nc.
// ---------------------------------------------------------------------------
constexpr int TP  = 128;
constexpr int TPB = 8;
constexpr int NCHUNK = L / (TP * TPB);   // 144
constexpr int XST = 132;                 // padded row stride (floats); 528B, 16B-aligned

__global__ __launch_bounds__(256, 3) void k_sums(const float* __restrict__ x,
                                                 const float* __restrict__ t,
                                                 const int* __restrict__ ncp) {
    __shared__ __align__(16) float pool[6144];   // tiles / reduction buffer union
    __shared__ unsigned char labels_s[TP];
    float* Xs = pool;                    // [16][132]
    float* Ts = pool + F * XST;          // [24][132]

    const int tid  = threadIdx.x;
    const int w    = tid >> 5;           // warp 0..7
    const int lane = tid & 31;
    const int b    = blockIdx.y;
    const int g    = tid >> 4;           // group 0..15
    const int fi   = tid & 15;           // feature row for compute phase
    const int nc   = __ldg(&ncp[b]);
    const float* xb = x + (size_t)(b * F) * L;
    const float* tb = t + (size_t)(b * K) * L;

    unsigned long long acc2[K];
#pragma unroll
    for (int c = 0; c < K; c++) acc2[c] = 0ull;
    float ts0 = 0.f, ts1 = 0.f, ts2 = 0.f;

    const int l0b = blockIdx.x * (TP * TPB);

    // x-load geometry: warp w owns feature rows 2w,2w+1; lanes 0-15 row 2w,
    // lanes 16-31 row 2w+1; one 256-bit evict_last load per lane (8 floats).
    const int xf_row = 2 * w + (lane >> 4);
    const int xoff   = (lane & 15) * 8;

    for (int tile = 0; tile < TPB; ++tile) {
        const int l0 = l0b + tile * TP;

        // ---- load x (256-bit, L2 evict_last) straight to smem ----
        {
            const float* p = xb + (size_t)xf_row * L + l0 + xoff;
            uint32_t r0, r1, r2, r3, r4, r5, r6, r7;
            asm volatile(
                "ld.global.L2::evict_last.v8.b32 {%0,%1,%2,%3,%4,%5,%6,%7}, [%8];"
                : "=r"(r0), "=r"(r1), "=r"(r2), "=r"(r3),
                  "=r"(r4), "=r"(r5), "=r"(r6), "=r"(r7)
                : "l"(p));
            uint4* s = (uint4*)(Xs + xf_row * XST + xoff);
            s[0] = make_uint4(r0, r1, r2, r3);
            s[1] = make_uint4(r4, r5, r6, r7);
        }
        // ---- load t rows 3w..3w+2, ONLY if row < nc (rows >= nc are zero) ----
#pragma unroll
        for (int r = 0; r < 3; r++) {
            const int c = 3 * w + r;
            if (c < nc) {
                float4 v = __ldcs((const float4*)(tb + (size_t)c * L + l0 + lane * 4));
                const float s = (v.x + v.y) + (v.z + v.w);
                if (r == 0) ts0 += s; else if (r == 1) ts1 += s; else ts2 += s;
                const int p0 = lane * 4;
                *(float4*)(Ts + c * XST + p0) = v;
                if (v.x != 0.f) labels_s[p0 + 0] = (unsigned char)c;
                if (v.y != 0.f) labels_s[p0 + 1] = (unsigned char)c;
                if (v.z != 0.f) labels_s[p0 + 2] = (unsigned char)c;
                if (v.w != 0.f) labels_s[p0 + 3] = (unsigned char)c;
            }
        }
        __syncthreads();

        // labels -> gmem (coalesced)
        if (tid < TP / 4) {
            uint32_t lv = *(const uint32_t*)&labels_s[tid * 4];
            *(uint32_t*)(g_labels + (size_t)b * L + l0 + tid * 4) = lv;
        }

        // ---- compute: packed f32x2 FFMA; early break at nc ----
        const float* Xrow = Xs + fi * XST;
#pragma unroll
        for (int qi = 0; qi < 2; ++qi) {
            const int q = (g * 2 + qi) * 4;
            const ulonglong2 xf = *(const ulonglong2*)(Xrow + q);
#pragma unroll
            for (int c = 0; c < K; c++) {
                if (c >= nc) break;                       // uniform per block
                const ulonglong2 tv = *(const ulonglong2*)(Ts + c * XST + q);
                asm("fma.rn.f32x2 %0, %1, %2, %0;"
                    : "+l"(acc2[c]) : "l"(xf.x), "l"(tv.x));
                asm("fma.rn.f32x2 %0, %1, %2, %0;"
                    : "+l"(acc2[c]) : "l"(xf.y), "l"(tv.y));
            }
        }
        __syncthreads();
    }

    // ---- block reduction of acc across the 16 groups ----
#pragma unroll
    for (int c = 0; c < K; c++) {
        const float lo = __uint_as_float((uint32_t)(acc2[c] & 0xffffffffull));
        const float hi = __uint_as_float((uint32_t)(acc2[c] >> 32));
        pool[tid * K + c] = lo + hi;
    }
    __syncthreads();
    for (int i = tid; i < F * K; i += 256) {      // F*K=384 > 256 threads
        const int f = i / K, c = i % K;
        if (c < nc) {
            float s = 0.f;
#pragma unroll
            for (int gg = 0; gg < 16; gg++) s += pool[(gg * 16 + f) * K + c];
            atomicAdd(&g_sums[(b * F + f) * K + c], s);
        }
    }
#pragma unroll
    for (int off = 16; off; off >>= 1) {
        ts0 += __shfl_down_sync(0xffffffffu, ts0, off);
        ts1 += __shfl_down_sync(0xffffffffu, ts1, off);
        ts2 += __shfl_down_sync(0xffffffffu, ts2, off);
    }
    if (lane == 0) {
        if (3 * w + 0 < nc) atomicAdd(&g_tsum[b * K + 3 * w + 0], ts0);
        if (3 * w + 1 < nc) atomicAdd(&g_tsum[b * K + 3 * w + 1], ts1);
        if (3 * w + 2 < nc) atomicAdd(&g_tsum[b * K + 3 * w + 2], ts2);
    }
}

// ---------------------------------------------------------------------------
// K2: means, m2, variance factor, pairwise-distance + reg terms.
// One block per b, 576 threads (= 24*24 pairs).
// ---------------------------------------------------------------------------
__global__ void k_means(const int* __restrict__ n_clusters) {
    __shared__ float ms[F * K];
    __shared__ float m2s[K];
    __shared__ float red[32];

    const int b   = blockIdx.x;
    const int tid = threadIdx.x;
    const int nc  = n_clusters[b];
    const float ncf = (float)nc;

    if (tid < F * K) {
        const int c = tid % K;
        float m = g_sums[b * F * K + tid] / (g_tsum[b * K + c] + EPSV);
        m = (c < nc) ? m : 0.f;
        ms[tid] = m;
        g_means[b * F * K + tid] = m;
    }
    __syncthreads();
    if (tid < K) {
        float m2 = 0.f;
#pragma unroll
        for (int f = 0; f < F; f++) { const float v = ms[f * K + tid]; m2 += v * v; }
        m2s[tid] = m2;
        g_m2[b * K + tid] = m2;
        const float ts = g_tsum[b * K + tid];
        g_factor[b * K + tid] = (tid < nc)
            ? (1.f / (ts + EPSV)) * (1.f / (ncf + EPSV)) * (1.f / (float)B) : 0.f;
    }
    __syncthreads();

    float regp = 0.f;
    if (tid < K && tid < nc) {
        const float m2 = m2s[tid];
        regp = (m2 > 0.f) ? sqrtf(m2) : 0.f;
    }
    float hs = 0.f;
    {
        const int cc = tid / K, dd = tid % K;
        if (cc != dd && cc < nc && dd < nc) {
            float mm = 0.f;
#pragma unroll
            for (int f = 0; f < F; f++) mm += ms[f * K + cc] * ms[f * K + dd];
            float pd2 = fmaxf(m2s[cc] - 2.f * mm + m2s[dd], 0.f);
            const float pdist = (pd2 > 0.f) ? sqrtf(pd2) : 0.f;
            const float h = fmaxf(2.f * DELTA_DIST - pdist, 0.f);
            hs = h * h;
        }
    }
    const int lane = tid & 31, wid = tid >> 5;   // 18 warps
#pragma unroll
    for (int off = 16; off; off >>= 1) hs += __shfl_down_sync(0xffffffffu, hs, off);
    if (lane == 0) red[wid] = hs;
    __syncthreads();
    float hs_tot = 0.f;
    if (tid < 32) {
        float v = (tid < 18) ? red[tid] : 0.f;
#pragma unroll
        for (int off = 16; off; off >>= 1) v += __shfl_down_sync(0xffffffffu, v, off);
        hs_tot = v;
    }
    __syncthreads();
#pragma unroll
    for (int off = 16; off; off >>= 1) regp += __shfl_down_sync(0xffffffffu, regp, off);
    if (lane == 0) red[wid] = regp;
    __syncthreads();
    if (tid == 0) {
        float reg_tot = 0.f;
        for (int i = 0; i < 18; i++) reg_tot += red[i];
        const float dist_per = hs_tot / (2.f * ncf * (ncf - 1.f) + EPSV);
        if (nc > 1) atomicAdd(&g_acc[0], dist_per / (float)B);
        if (nc > 0) atomicAdd(&g_acc[1], reg_tot / ncf / (float)B);
    }
}

// ---------------------------------------------------------------------------
// K3: variance term, fully folded: pixel adds h^2 * factor[label] to a scalar;
// block reduce -> 1 global atomic; last block writes the output.
// ---------------------------------------------------------------------------
__global__ __launch_bounds__(256) void k_var(const float* __restrict__ x,
                                             float* __restrict__ out) {
    __shared__ float ms[F * K];
    __shared__ float m2s[K];
    __shared__ float fac[K];
    __shared__ float red[8];

    const int b   = blockIdx.y;
    const int tid = threadIdx.x;
    for (int i = tid; i < F * K; i += 256) ms[i] = g_means[b * F * K + i];
    if (tid < K) { m2s[tid] = g_m2[b * K + tid]; fac[tid] = g_factor[b * K + tid]; }
    __syncthreads();

    const int l = blockIdx.x * 1024 + tid * 4;
    const uint32_t lab4 = __ldg((const uint32_t*)(g_labels + (size_t)b * L + l));
    const int lab0 = (int)(lab4 & 255),        lab1 = (int)((lab4 >> 8) & 255);
    const int lab2 = (int)((lab4 >> 16) & 255), lab3 = (int)((lab4 >> 24) & 255);

    float x20 = 0.f, x21 = 0.f, x22 = 0.f, x23 = 0.f;
    float xm0 = 0.f, xm1 = 0.f, xm2 = 0.f, xm3 = 0.f;
    const float* xb = x + (size_t)(b * F) * L + l;
    const float* ms0 = ms + lab0; const float* ms1 = ms + lab1;
    const float* ms2 = ms + lab2; const float* ms3 = ms + lab3;
#pragma unroll
    for (int f = 0; f < F; f++) {
        const float4 v = __ldg((const float4*)(xb + (size_t)f * L));
        x20 += v.x * v.x;  xm0 += v.x * ms0[f * K];
        x21 += v.y * v.y;  xm1 += v.y * ms1[f * K];
        x22 += v.z * v.z;  xm2 += v.z * ms2[f * K];
        x23 += v.w * v.w;  xm3 += v.w * ms3[f * K];
    }
    float a = 0.f;
    {
        float d2 = fmaxf(x20 - 2.f * xm0 + m2s[lab0], 0.f);
        float h = ((d2 > 0.f) ? sqrtf(d2) : 0.f) - DELTA_VAR;
        if (h > 0.f) a += h * h * fac[lab0];
        d2 = fmaxf(x21 - 2.f * xm1 + m2s[lab1], 0.f);
        h = ((d2 > 0.f) ? sqrtf(d2) : 0.f) - DELTA_VAR;
        if (h > 0.f) a += h * h * fac[lab1];
        d2 = fmaxf(x22 - 2.f * xm2 + m2s[lab2], 0.f);
        h = ((d2 > 0.f) ? sqrtf(d2) : 0.f) - DELTA_VAR;
        if (h > 0.f) a += h * h * fac[lab2];
        d2 = fmaxf(x23 - 2.f * xm3 + m2s[lab3], 0.f);
        h = ((d2 > 0.f) ? sqrtf(d2) : 0.f) - DELTA_VAR;
        if (h > 0.f) a += h * h * fac[lab3];
    }
    const int lane = tid & 31, wid = tid >> 5;
#pragma unroll
    for (int off = 16; off; off >>= 1) a += __shfl_down_sync(0xffffffffu, a, off);
    if (lane == 0) red[wid] = a;
    __syncthreads();
    if (tid == 0) {
        float s = 0.f;
#pragma unroll
        for (int i = 0; i < 8; i++) s += red[i];
        atomicAdd(&g_acc[2], s);
        __threadfence();
        const unsigned t = atomicAdd(&g_ticket, 1u);
        if (t == (unsigned)(NCHUNK * B) - 1u) {
            volatile float* ga = g_acc;
            out[0] = ga[2] + ga[0] + GAMMA * ga[1];
        }
    }
}

// ---------------------------------------------------------------------------
extern "C" void kernel_launch(void* const* d_in, const int* in_sizes, int n_in,
                              void* d_out, int out_size) {
    const float* x  = (const float*)d_in[0];
    const float* t  = (const float*)d_in[1];
    const int*   nc = (const int*)d_in[2];
    float* out = (float*)d_out;

    k_init<<<12, 256>>>();
    k_sums<<<dim3(NCHUNK, B), 256>>>(x, t, nc);
    k_means<<<B, 576>>>(nc);
    k_var<<<dim3(NCHUNK, B), 256>>>(x, out);
}

// round 6
// speedup vs baseline: 1.7038x; 1.3321x over previous
#include <cuda_runtime.h>
#include <cstdint>

constexpr int   B = 8, F = 16, K = 24;
constexpr int   L = 384 * 384;          // 147456 pixels per (b, plane)
constexpr float EPSV       = 1e-8f;
constexpr float DELTA_VAR  = 0.5f;
constexpr float DELTA_DIST = 1.5f;
constexpr float GAMMA      = 0.001f;

// Scratch (device globals; statically zero-initialized for the first call,
// re-zeroed by the last k_var block for subsequent graph replays)
__device__ float g_sums[B * F * K];
__device__ float g_tsum[B * K];
__device__ float g_means[B * F * K];
__device__ float g_m2[B * K];
__device__ float g_factor[B * K];
__device__ float g_acc[4];              // [0]=dist/B [1]=reg/B [2]=var accumulator
__device__ unsigned g_ticket;
__device__ unsigned char g_labels[B * L];

// ---------------------------------------------------------------------------
// K1: sums[b,f,c] = sum_l x[b,f,l]*t[b,c,l];  t_sum; labels.
// t rows c >= n_clusters[b] are all-zero -> neither loaded nor multiplied.
// Deferred-STS register staging pipelines DRAM latency against f32x2 compute.
// ---------------------------------------------------------------------------
constexpr int TP  = 128;
constexpr int TPB = 8;
constexpr int NCHUNK = L / (TP * TPB);   // 144
constexpr int XST = 132;                 // padded row stride (floats); conflict-free

__global__ __launch_bounds__(256, 2) void k_sums(const float* __restrict__ x,
                                                 const float* __restrict__ t,
                                                 const int* __restrict__ ncp) {
    __shared__ __align__(16) float pool[6144];   // tiles / reduction buffer union
    __shared__ unsigned char labels_s[TP];
    float* Xs = pool;                    // [16][132]
    float* Ts = pool + F * XST;          // [24][132]

    const int tid  = threadIdx.x;
    const int w    = tid >> 5;           // warp 0..7
    const int lane = tid & 31;
    const int b    = blockIdx.y;
    const int g    = tid >> 4;           // group 0..15
    const int fi   = tid & 15;           // feature row for compute phase
    const int nc   = __ldg(&ncp[b]);
    const int nc4  = (nc + 3) & ~3;      // break granularity (padded accs unused)
    const float* xb = x + (size_t)(b * F) * L;
    const float* tb = t + (size_t)(b * K) * L;

    unsigned long long acc2[K];
#pragma unroll
    for (int c = 0; c < K; c++) acc2[c] = 0ull;
    float ts0 = 0.f, ts1 = 0.f, ts2 = 0.f;

    const int l0b = blockIdx.x * (TP * TPB);

    // x-load geometry: warp w owns feature rows 2w,2w+1; lanes 0-15 row 2w,
    // lanes 16-31 row 2w+1; one 256-bit evict_last load per lane (8 floats).
    const int xf_row = 2 * w + (lane >> 4);
    const int xoff   = (lane & 15) * 8;
    const int c0 = 3 * w, c1 = 3 * w + 1, c2 = 3 * w + 2;
    const bool v0 = c0 < nc, v1 = c1 < nc, v2 = c2 < nc;

    uint32_t xr[8];                       // staging regs (tile t while computing t-1)
    float4 tr0, tr1, tr2;

#define LOAD_TILE(L0)                                                          \
    {                                                                          \
        const float* p = xb + (size_t)xf_row * L + (L0) + xoff;                \
        asm volatile(                                                          \
            "ld.global.L2::evict_last.v8.b32 {%0,%1,%2,%3,%4,%5,%6,%7}, [%8];" \
            : "=r"(xr[0]), "=r"(xr[1]), "=r"(xr[2]), "=r"(xr[3]),              \
              "=r"(xr[4]), "=r"(xr[5]), "=r"(xr[6]), "=r"(xr[7])               \
            : "l"(p));                                                         \
        if (v0) tr0 = __ldcs((const float4*)(tb + (size_t)c0 * L + (L0) + lane * 4)); \
        if (v1) tr1 = __ldcs((const float4*)(tb + (size_t)c1 * L + (L0) + lane * 4)); \
        if (v2) tr2 = __ldcs((const float4*)(tb + (size_t)c2 * L + (L0) + lane * 4)); \
    }

    LOAD_TILE(l0b);

#pragma unroll 1
    for (int tile = 0; tile < TPB; ++tile) {
        const int l0 = l0b + tile * TP;

        // ---- drain staged regs to smem; labels + t_sum from regs ----
        {
            uint4* s = (uint4*)(Xs + xf_row * XST + xoff);
            s[0] = make_uint4(xr[0], xr[1], xr[2], xr[3]);
            s[1] = make_uint4(xr[4], xr[5], xr[6], xr[7]);

            const int p0 = lane * 4;
            if (v0) {
                const float4 v = tr0;
                ts0 += (v.x + v.y) + (v.z + v.w);
                *(float4*)(Ts + c0 * XST + p0) = v;
                if (v.x != 0.f) labels_s[p0 + 0] = (unsigned char)c0;
                if (v.y != 0.f) labels_s[p0 + 1] = (unsigned char)c0;
                if (v.z != 0.f) labels_s[p0 + 2] = (unsigned char)c0;
                if (v.w != 0.f) labels_s[p0 + 3] = (unsigned char)c0;
            }
            if (v1) {
                const float4 v = tr1;
                ts1 += (v.x + v.y) + (v.z + v.w);
                *(float4*)(Ts + c1 * XST + p0) = v;
                if (v.x != 0.f) labels_s[p0 + 0] = (unsigned char)c1;
                if (v.y != 0.f) labels_s[p0 + 1] = (unsigned char)c1;
                if (v.z != 0.f) labels_s[p0 + 2] = (unsigned char)c1;
                if (v.w != 0.f) labels_s[p0 + 3] = (unsigned char)c1;
            }
            if (v2) {
                const float4 v = tr2;
                ts2 += (v.x + v.y) + (v.z + v.w);
                *(float4*)(Ts + c2 * XST + p0) = v;
                if (v.x != 0.f) labels_s[p0 + 0] = (unsigned char)c2;
                if (v.y != 0.f) labels_s[p0 + 1] = (unsigned char)c2;
                if (v.z != 0.f) labels_s[p0 + 2] = (unsigned char)c2;
                if (v.w != 0.f) labels_s[p0 + 3] = (unsigned char)c2;
            }
        }
        __syncthreads();

        // labels -> gmem (coalesced)
        if (tid < TP / 4) {
            uint32_t lv = *(const uint32_t*)&labels_s[tid * 4];
            *(uint32_t*)(g_labels + (size_t)b * L + l0 + tid * 4) = lv;
        }

        // prefetch next tile into staging regs (overlaps compute below)
        if (tile + 1 < TPB) LOAD_TILE(l0 + TP);

        // ---- compute: packed f32x2 FFMA over both quads; break every 4 c ----
        {
            const float* Xrow = Xs + fi * XST;
            const int q0 = g * 8;                       // float offset of quad pair
            const ulonglong2 xf0 = *(const ulonglong2*)(Xrow + q0);
            const ulonglong2 xf1 = *(const ulonglong2*)(Xrow + q0 + 4);
#pragma unroll
            for (int c = 0; c < K; c++) {
                if ((c & 3) == 0 && c >= nc4) break;    // uniform per block
                const float* Trow = Ts + c * XST + q0;
                const ulonglong2 tv0 = *(const ulonglong2*)(Trow);
                const ulonglong2 tv1 = *(const ulonglong2*)(Trow + 4);
                asm("fma.rn.f32x2 %0, %1, %2, %0;" : "+l"(acc2[c]) : "l"(xf0.x), "l"(tv0.x));
                asm("fma.rn.f32x2 %0, %1, %2, %0;" : "+l"(acc2[c]) : "l"(xf0.y), "l"(tv0.y));
                asm("fma.rn.f32x2 %0, %1, %2, %0;" : "+l"(acc2[c]) : "l"(xf1.x), "l"(tv1.x));
                asm("fma.rn.f32x2 %0, %1, %2, %0;" : "+l"(acc2[c]) : "l"(xf1.y), "l"(tv1.y));
            }
        }
        __syncthreads();
    }
#undef LOAD_TILE

    // ---- block reduction of acc across the 16 groups ----
#pragma unroll
    for (int c = 0; c < K; c++) {
        const float lo = __uint_as_float((uint32_t)(acc2[c] & 0xffffffffull));
        const float hi = __uint_as_float((uint32_t)(acc2[c] >> 32));
        pool[tid * K + c] = lo + hi;
    }
    __syncthreads();
    for (int i = tid; i < F * K; i += 256) {      // F*K=384 > 256 threads
        const int f = i / K, c = i % K;
        if (c < nc) {
            float s = 0.f;
#pragma unroll
            for (int gg = 0; gg < 16; gg++) s += pool[(gg * 16 + f) * K + c];
            atomicAdd(&g_sums[(b * F + f) * K + c], s);
        }
    }
#pragma unroll
    for (int off = 16; off; off >>= 1) {
        ts0 += __shfl_down_sync(0xffffffffu, ts0, off);
        ts1 += __shfl_down_sync(0xffffffffu, ts1, off);
        ts2 += __shfl_down_sync(0xffffffffu, ts2, off);
    }
    if (lane == 0) {
        if (v0) atomicAdd(&g_tsum[b * K + c0], ts0);
        if (v1) atomicAdd(&g_tsum[b * K + c1], ts1);
        if (v2) atomicAdd(&g_tsum[b * K + c2], ts2);
    }
}

// ---------------------------------------------------------------------------
// K2: means, m2, variance factor, pairwise-distance + reg terms.
// ---------------------------------------------------------------------------
__global__ void k_means(const int* __restrict__ n_clusters) {
    __shared__ float ms[F * K];
    __shared__ float m2s[K];
    __shared__ float red[32];

    const int b   = blockIdx.x;
    const int tid = threadIdx.x;
    const int nc  = n_clusters[b];
    const float ncf = (float)nc;

    if (tid < F * K) {
        const int c = tid % K;
        float m = g_sums[b * F * K + tid] / (g_tsum[b * K + c] + EPSV);
        m = (c < nc) ? m : 0.f;
        ms[tid] = m;
        g_means[b * F * K + tid] = m;
    }
    __syncthreads();
    if (tid < K) {
        float m2 = 0.f;
#pragma unroll
        for (int f = 0; f < F; f++) { const float v = ms[f * K + tid]; m2 += v * v; }
        m2s[tid] = m2;
        g_m2[b * K + tid] = m2;
        const float ts = g_tsum[b * K + tid];
        g_factor[b * K + tid] = (tid < nc)
            ? (1.f / (ts + EPSV)) * (1.f / (ncf + EPSV)) * (1.f / (float)B) : 0.f;
    }
    __syncthreads();

    float regp = 0.f;
    if (tid < K && tid < nc) {
        const float m2 = m2s[tid];
        regp = (m2 > 0.f) ? sqrtf(m2) : 0.f;
    }
    float hs = 0.f;
    {
        const int cc = tid / K, dd = tid % K;
        if (cc != dd && cc < nc && dd < nc) {
            float mm = 0.f;
#pragma unroll
            for (int f = 0; f < F; f++) mm += ms[f * K + cc] * ms[f * K + dd];
            float pd2 = fmaxf(m2s[cc] - 2.f * mm + m2s[dd], 0.f);
            const float pdist = (pd2 > 0.f) ? sqrtf(pd2) : 0.f;
            const float h = fmaxf(2.f * DELTA_DIST - pdist, 0.f);
            hs = h * h;
        }
    }
    const int lane = tid & 31, wid = tid >> 5;   // 18 warps
#pragma unroll
    for (int off = 16; off; off >>= 1) hs += __shfl_down_sync(0xffffffffu, hs, off);
    if (lane == 0) red[wid] = hs;
    __syncthreads();
    float hs_tot = 0.f;
    if (tid < 32) {
        float v = (tid < 18) ? red[tid] : 0.f;
#pragma unroll
        for (int off = 16; off; off >>= 1) v += __shfl_down_sync(0xffffffffu, v, off);
        hs_tot = v;
    }
    __syncthreads();
#pragma unroll
    for (int off = 16; off; off >>= 1) regp += __shfl_down_sync(0xffffffffu, regp, off);
    if (lane == 0) red[wid] = regp;
    __syncthreads();
    if (tid == 0) {
        float reg_tot = 0.f;
        for (int i = 0; i < 18; i++) reg_tot += red[i];
        const float dist_per = hs_tot / (2.f * ncf * (ncf - 1.f) + EPSV);
        if (nc > 1) atomicAdd(&g_acc[0], dist_per / (float)B);
        if (nc > 0) atomicAdd(&g_acc[1], reg_tot / ncf / (float)B);
    }
}

// ---------------------------------------------------------------------------
// K3: variance term. 8 pixels/thread via 256-bit loads; block reduce -> one
// atomic. Last block writes out AND re-zeroes scratch for the next replay.
// grid (72, 8), 256 threads.
// ---------------------------------------------------------------------------
constexpr int VBLK = L / (256 * 8);      // 72

__global__ __launch_bounds__(256) void k_var(const float* __restrict__ x,
                                             float* __restrict__ out) {
    __shared__ float ms[F * K];
    __shared__ float m2s[K];
    __shared__ float fac[K];
    __shared__ float red[8];
    __shared__ int amLast;

    const int b   = blockIdx.y;
    const int tid = threadIdx.x;
    for (int i = tid; i < F * K; i += 256) ms[i] = g_means[b * F * K + i];
    if (tid < K) { m2s[tid] = g_m2[b * K + tid]; fac[tid] = g_factor[b * K + tid]; }
    __syncthreads();

    const int l = (blockIdx.x * 256 + tid) * 8;
    const uint2 lw = __ldg((const uint2*)(g_labels + (size_t)b * L + l));
    int lab[8];
    lab[0] = (int)(lw.x & 255);  lab[1] = (int)((lw.x >> 8) & 255);
    lab[2] = (int)((lw.x >> 16) & 255);  lab[3] = (int)((lw.x >> 24) & 255);
    lab[4] = (int)(lw.y & 255);  lab[5] = (int)((lw.y >> 8) & 255);
    lab[6] = (int)((lw.y >> 16) & 255);  lab[7] = (int)((lw.y >> 24) & 255);

    float x2[8], xm[8];
#pragma unroll
    for (int j = 0; j < 8; j++) { x2[j] = 0.f; xm[j] = 0.f; }

    const float* xb = x + (size_t)(b * F) * L + l;
#pragma unroll
    for (int f = 0; f < F; f++) {
        float v[8];
        asm("ld.global.v8.b32 {%0,%1,%2,%3,%4,%5,%6,%7}, [%8];"
            : "=f"(v[0]), "=f"(v[1]), "=f"(v[2]), "=f"(v[3]),
              "=f"(v[4]), "=f"(v[5]), "=f"(v[6]), "=f"(v[7])
            : "l"(xb + (size_t)f * L));
        const float* msf = ms + f * K;
#pragma unroll
        for (int j = 0; j < 8; j++) {
            x2[j] += v[j] * v[j];
            xm[j] += v[j] * msf[lab[j]];
        }
    }
    float a = 0.f;
#pragma unroll
    for (int j = 0; j < 8; j++) {
        const float d2 = fmaxf(x2[j] - 2.f * xm[j] + m2s[lab[j]], 0.f);
        const float h = ((d2 > 0.f) ? sqrtf(d2) : 0.f) - DELTA_VAR;
        if (h > 0.f) a += h * h * fac[lab[j]];
    }
    const int lane = tid & 31, wid = tid >> 5;
#pragma unroll
    for (int off = 16; off; off >>= 1) a += __shfl_down_sync(0xffffffffu, a, off);
    if (lane == 0) red[wid] = a;
    __syncthreads();
    if (tid == 0) {
        float s = 0.f;
#pragma unroll
        for (int i = 0; i < 8; i++) s += red[i];
        atomicAdd(&g_acc[2], s);
        __threadfence();
        const unsigned t = atomicAdd(&g_ticket, 1u);
        amLast = (t == (unsigned)(VBLK * B) - 1u) ? 1 : 0;
    }
    __syncthreads();
    if (amLast) {
        // finalize + re-zero scratch for the next graph replay
        if (tid == 0) {
            volatile float* ga = g_acc;
            out[0] = ga[2] + ga[0] + GAMMA * ga[1];
            g_acc[0] = 0.f; g_acc[1] = 0.f; g_acc[2] = 0.f; g_acc[3] = 0.f;
            g_ticket = 0u;
        }
        for (int i = tid; i < B * F * K; i += 256) g_sums[i] = 0.f;
        for (int i = tid; i < B * K; i += 256) g_tsum[i] = 0.f;
    }
}

// ---------------------------------------------------------------------------
extern "C" void kernel_launch(void* const* d_in, const int* in_sizes, int n_in,
                              void* d_out, int out_size) {
    const float* x  = (const float*)d_in[0];
    const float* t  = (const float*)d_in[1];
    const int*   nc = (const int*)d_in[2];
    float* out = (float*)d_out;

    k_sums<<<dim3(NCHUNK, B), 256>>>(x, t, nc);
    k_means<<<B, 576>>>(nc);
    k_var<<<dim3(VBLK, B), 256>>>(x, out);
}